// round 15
// baseline (speedup 1.0000x reference)
#include <cuda_runtime.h>
#include <math.h>

// ---------------------------------------------------------------------------
// TextureBaker — 2 kernels (R14 structure, register-trimmed for 5 blocks/SM).
//  1) tb_setup : per-triangle setup -> 48B record (+tri id), ids, bbox.
//  2) tb_bake  : block = 16x32 pixel tile, 256 threads, 2 vertical px/thread.
//       Phase A : bbox rejection, stable compaction.
//       Phase A2: SAT refine on bbox survivors, stable compaction.
//       Phase B : cooperative copy of surviving 48B records into smem.
//       Phase C : dual-pixel first-hit scan; ONLY the hit triangle id is kept
//                 (u,v,w recomputed bit-identically in the epilogue from
//                 g_rec[hit]) -> fewer live registers -> 5 blocks/SM.
//  Bake launched with PDL; gates on cudaGridDependencySynchronize().
// ---------------------------------------------------------------------------

#define MAX_F  8192
#define TSX    16
#define TSY    32
#define SCAP   256     // records per smem scan batch

__device__ float4 g_rec [MAX_F * 3];  // [ax ay v0x v0y][v1x v1y d00 d01][d11 inv tid 0]
__device__ int4   g_ids [MAX_F];
__device__ float4 g_bbox[MAX_F];      // (minx, maxx, miny, maxy)

// ------------------------------- setup ------------------------------------
__global__ void tb_setup_kernel(const float* __restrict__ uv,
                                const int*   __restrict__ fidx,
                                int nf)
{
    int t = blockIdx.x * blockDim.x + threadIdx.x;
    if (t >= nf) return;

    int i0 = fidx[3 * t + 0];
    int i1 = fidx[3 * t + 1];
    int i2 = fidx[3 * t + 2];

    float ax = uv[2 * i0], ay = uv[2 * i0 + 1];
    float bx = uv[2 * i1], by = uv[2 * i1 + 1];
    float cx = uv[2 * i2], cy = uv[2 * i2 + 1];

    float v0x = bx - ax, v0y = by - ay;
    float v1x = cx - ax, v1y = cy - ay;

    float d00 = v0x * v0x + v0y * v0y;
    float d01 = v0x * v1x + v0y * v1y;
    float d11 = v1x * v1x + v1y * v1y;
    float denom = d00 * d11 - d01 * d01;

    // Degenerate triangle -> NaN inv -> inside test always false (matches ref).
    float inv = (fabsf(denom) < 1e-12f) ? __int_as_float(0x7fc00000)
                                        : (1.0f / denom);

    g_rec[3 * t + 0] = make_float4(ax, ay, v0x, v0y);
    g_rec[3 * t + 1] = make_float4(v1x, v1y, d00, d01);
    g_rec[3 * t + 2] = make_float4(d11, inv, __int_as_float(t), 0.0f);
    g_ids[t] = make_int4(i0, i1, i2, 0);

    float4 bb;
    bb.x = fminf(ax, fminf(bx, cx));
    bb.y = fmaxf(ax, fmaxf(bx, cx));
    bb.z = fminf(ay, fminf(by, cy));
    bb.w = fmaxf(ay, fmaxf(by, cy));
    g_bbox[t] = bb;
}

// ----------------------------- SAT helper ---------------------------------
__device__ __forceinline__ bool rect_outside_edge(
    float px, float py, float qx, float qy, float rx, float ry,
    float x0, float y0, float x1, float y1)
{
    float ex = qx - px, ey = qy - py;
    float sr  = ex * (ry - py) - ey * (rx - px);
    float s00 = ex * (y0 - py) - ey * (x0 - px);
    float s01 = ex * (y1 - py) - ey * (x0 - px);
    float s10 = ex * (y0 - py) - ey * (x1 - px);
    float s11 = ex * (y1 - py) - ey * (x1 - px);
    float mx = fmaxf(fmaxf(s00, s01), fmaxf(s10, s11));
    float mn = fminf(fminf(s00, s01), fminf(s10, s11));
    if (sr > 0.0f) return mx < 0.0f;   // whole rect strictly on far side
    if (sr < 0.0f) return mn > 0.0f;
    return false;                      // degenerate edge: keep (conservative)
}

// -------------------------------- bake ------------------------------------
__global__ void __launch_bounds__(256, 5)
tb_bake_kernel(const float* __restrict__ attr,
               int nf, int res, int ntx,
               float* __restrict__ out)
{
    __shared__ float4 s_rec[SCAP * 3];  // 12 KB
    __shared__ int    s_idx [512];
    __shared__ int    s_idx2[512];
    __shared__ int    s_tot[16];

    int tile = blockIdx.x;
    int tx = tile % ntx;
    int ty = tile / ntx;
    int tid  = threadIdx.x;
    int lane = tid & 31;
    int wid  = tid >> 5;
    unsigned lmask = (1u << lane) - 1u;

    const float eps = 1e-5f;
    float rinv = 1.0f / (float)res;
    float x0 = (float)(tx * TSX)       * rinv - eps;
    float x1 = (float)(tx * TSX + TSX) * rinv + eps;
    float y0 = (float)(ty * TSY)       * rinv - eps;
    float y1 = (float)(ty * TSY + TSY) * rinv + eps;

    // two vertically adjacent pixels per thread
    int col  = tx * TSX + (tid & (TSX - 1));
    int rowA = ty * TSY + ((tid >> 4) << 1);
    int rowB = rowA + 1;
    bool validA = (col < res) && (rowA < res);
    bool validB = (col < res) && (rowB < res);

    float pxx  = ((float)col  + 0.5f) * rinv;
    float pxyA = ((float)rowA + 0.5f) * rinv;
    float pxyB = ((float)rowB + 0.5f) * rinv;

    // hit sentinel also encodes "done": -1 = still searching, -2 = invalid px
    int hitA = validA ? -1 : -2;
    int hitB = validB ? -1 : -2;

    // PDL: wait for setup outputs before reading g_* arrays.
    cudaGridDependencySynchronize();

    for (int chunk = 0; chunk < nf; chunk += 512) {
        __syncthreads();

        // ---- Phase A: bbox rejection, combined stable compaction ----
        int t0 = chunk + tid;
        int t1 = t0 + 256;
        bool k0 = false, k1 = false;
        if (t0 < nf) {
            float4 bb = g_bbox[t0];
            k0 = !(bb.x > x1 || bb.y < x0 || bb.z > y1 || bb.w < y0);
        }
        if (t1 < nf) {
            float4 bb = g_bbox[t1];
            k1 = !(bb.x > x1 || bb.y < x0 || bb.z > y1 || bb.w < y0);
        }
        unsigned b0 = __ballot_sync(0xffffffffu, k0);
        unsigned b1 = __ballot_sync(0xffffffffu, k1);
        if (lane == 0) { s_tot[wid] = __popc(b0); s_tot[8 + wid] = __popc(b1); }
        __syncthreads();

        int pre0 = 0, tot0 = 0, pre1 = 0, tot1 = 0;
        #pragma unroll
        for (int k = 0; k < 8; k++) {
            int a = s_tot[k], b = s_tot[8 + k];
            tot0 += a; tot1 += b;
            pre0 += (k < wid) ? a : 0;
            pre1 += (k < wid) ? b : 0;
        }
        if (k0) s_idx[pre0 + __popc(b0 & lmask)] = t0;
        if (k1) s_idx[tot0 + pre1 + __popc(b1 & lmask)] = t1;
        __syncthreads();
        int bn = tot0 + tot1;

        // ---- Phase A2: SAT refine on bbox survivors ----
        int bn2 = 0;
        for (int base = 0; base < bn; base += 256) {
            int  e = base + tid;
            bool keep = false;
            if (e < bn) {
                int t = s_idx[e];
                float4 a4 = g_rec[3 * t + 0];           // ax ay v0x v0y
                float4 b4 = g_rec[3 * t + 1];           // v1x v1y d00 d01
                float ax = a4.x,        ay = a4.y;
                float bx = ax + a4.z,   by = ay + a4.w;
                float cx = ax + b4.x,   cy = ay + b4.y;
                keep = !(rect_outside_edge(ax, ay, bx, by, cx, cy, x0, y0, x1, y1) ||
                         rect_outside_edge(bx, by, cx, cy, ax, ay, x0, y0, x1, y1) ||
                         rect_outside_edge(cx, cy, ax, ay, bx, by, x0, y0, x1, y1));
            }
            unsigned bal = __ballot_sync(0xffffffffu, keep);
            if (lane == 0) s_tot[wid] = __popc(bal);
            __syncthreads();
            int pre = 0, tot = 0;
            #pragma unroll
            for (int k = 0; k < 8; k++) {
                int a = s_tot[k];
                tot += a;
                pre += (k < wid) ? a : 0;
            }
            if (keep) s_idx2[bn2 + pre + __popc(bal & lmask)] = s_idx[e];
            __syncthreads();
            bn2 += tot;
        }

        // ---- Phase B + C: batched cooperative copy + dual-pixel scan ----
        for (int base = 0; base < bn2; base += SCAP) {
            int m = min(SCAP, bn2 - base);

            __syncthreads();
            for (int rr = tid; rr < m; rr += 256) {
                int t = s_idx2[base + rr];
                s_rec[3 * rr + 0] = g_rec[3 * t + 0];
                s_rec[3 * rr + 1] = g_rec[3 * t + 1];
                s_rec[3 * rr + 2] = g_rec[3 * t + 2];
            }
            __syncthreads();

            if (hitA == -1 || hitB == -1) {
                for (int j = 0; j < m; j++) {
                    float4 q0 = s_rec[3 * j + 0];   // ax ay v0x v0y
                    float4 q1 = s_rec[3 * j + 1];   // v1x v1y d00 d01
                    float4 q2 = s_rec[3 * j + 2];   // d11 inv tid 0

                    float v2x = pxx - q0.x;
                    float d20x = v2x * q0.z;
                    float d21x = v2x * q1.x;

                    if (hitA == -1) {
                        float v2y = pxyA - q0.y;
                        float d20 = d20x + v2y * q0.w;
                        float d21 = d21x + v2y * q1.y;
                        float vv  = (q2.x * d20 - q1.w * d21) * q2.y;
                        float ww  = (q1.z * d21 - q1.w * d20) * q2.y;
                        float uu  = 1.0f - vv - ww;
                        if (uu >= 0.0f && vv >= 0.0f && ww >= 0.0f)
                            hitA = __float_as_int(q2.z);
                    }
                    if (hitB == -1) {
                        float v2y = pxyB - q0.y;
                        float d20 = d20x + v2y * q0.w;
                        float d21 = d21x + v2y * q1.y;
                        float vv  = (q2.x * d20 - q1.w * d21) * q2.y;
                        float ww  = (q1.z * d21 - q1.w * d20) * q2.y;
                        float uu  = 1.0f - vv - ww;
                        if (uu >= 0.0f && vv >= 0.0f && ww >= 0.0f)
                            hitB = __float_as_int(q2.z);
                    }
                    if (hitA != -1 && hitB != -1) break;
                }
            }
            if (__syncthreads_and(hitA != -1 && hitB != -1)) break;
        }
        if (__syncthreads_and(hitA != -1 && hitB != -1)) break;
    }

    // ---- epilogue: recompute (u,v,w) bit-identically from g_rec[hit] ----
    if (validA) {
        float o0 = 0.0f, o1 = 0.0f, o2 = 0.0f;
        if (hitA >= 0) {
            float4 q0 = g_rec[3 * hitA + 0];
            float4 q1 = g_rec[3 * hitA + 1];
            float4 q2 = g_rec[3 * hitA + 2];
            float v2x = pxx - q0.x;
            float d20x = v2x * q0.z;
            float d21x = v2x * q1.x;
            float v2y = pxyA - q0.y;
            float d20 = d20x + v2y * q0.w;
            float d21 = d21x + v2y * q1.y;
            float vv  = (q2.x * d20 - q1.w * d21) * q2.y;
            float ww  = (q1.z * d21 - q1.w * d20) * q2.y;
            float uu  = 1.0f - vv - ww;
            int4 ids = g_ids[hitA];
            const float* a0 = attr + 3 * ids.x;
            const float* a1 = attr + 3 * ids.y;
            const float* a2 = attr + 3 * ids.z;
            o0 = uu * a0[0] + vv * a1[0] + ww * a2[0];
            o1 = uu * a0[1] + vv * a1[1] + ww * a2[1];
            o2 = uu * a0[2] + vv * a1[2] + ww * a2[2];
        }
        int pix = rowA * res + col;
        out[3 * pix + 0] = o0;
        out[3 * pix + 1] = o1;
        out[3 * pix + 2] = o2;
    }
    if (validB) {
        float o0 = 0.0f, o1 = 0.0f, o2 = 0.0f;
        if (hitB >= 0) {
            float4 q0 = g_rec[3 * hitB + 0];
            float4 q1 = g_rec[3 * hitB + 1];
            float4 q2 = g_rec[3 * hitB + 2];
            float v2x = pxx - q0.x;
            float d20x = v2x * q0.z;
            float d21x = v2x * q1.x;
            float v2y = pxyB - q0.y;
            float d20 = d20x + v2y * q0.w;
            float d21 = d21x + v2y * q1.y;
            float vv  = (q2.x * d20 - q1.w * d21) * q2.y;
            float ww  = (q1.z * d21 - q1.w * d20) * q2.y;
            float uu  = 1.0f - vv - ww;
            int4 ids = g_ids[hitB];
            const float* a0 = attr + 3 * ids.x;
            const float* a1 = attr + 3 * ids.y;
            const float* a2 = attr + 3 * ids.z;
            o0 = uu * a0[0] + vv * a1[0] + ww * a2[0];
            o1 = uu * a0[1] + vv * a1[1] + ww * a2[1];
            o2 = uu * a0[2] + vv * a1[2] + ww * a2[2];
        }
        int pix = rowB * res + col;
        out[3 * pix + 0] = o0;
        out[3 * pix + 1] = o1;
        out[3 * pix + 2] = o2;
    }
}

// ------------------------------- launch -----------------------------------
extern "C" void kernel_launch(void* const* d_in, const int* in_sizes, int n_in,
                              void* d_out, int out_size)
{
    const float* attr = (const float*)d_in[0];
    const float* uv   = (const float*)d_in[1];
    const int*   fidx = (const int*)  d_in[2];
    float*       out  = (float*)      d_out;

    int nf = in_sizes[2] / 3;
    int nf_used = (nf / 64) * 64;          // reference truncates to chunks of 64
    if (nf_used > MAX_F) nf_used = MAX_F;

    int res = (int)(sqrt((double)out_size / 3.0) + 0.5);
    int ntx = (res + TSX - 1) / TSX;
    int nty = (res + TSY - 1) / TSY;
    int ntiles = ntx * nty;

    if (nf_used > 0) {
        int sblocks = (nf_used + 127) / 128;
        tb_setup_kernel<<<sblocks, 128>>>(uv, fidx, nf_used);
    }

    // PDL launch: overlap bake prologue with setup.
    cudaLaunchConfig_t cfg = {};
    cfg.gridDim  = dim3((unsigned)ntiles, 1, 1);
    cfg.blockDim = dim3(256, 1, 1);
    cfg.dynamicSmemBytes = 0;
    cfg.stream = 0;
    cudaLaunchAttribute at[1];
    at[0].id = cudaLaunchAttributeProgrammaticStreamSerialization;
    at[0].val.programmaticStreamSerializationAllowed = 1;
    cfg.attrs = at;
    cfg.numAttrs = 1;
    cudaLaunchKernelEx(&cfg, tb_bake_kernel, attr, nf_used, res, ntx, out);
}